// round 2
// baseline (speedup 1.0000x reference)
#include <cuda_runtime.h>
#include <math.h>

#define T_SAMPLES 128
#define HID 16
#define HPAIRS (HID / 2)

typedef unsigned long long u64;

// ---- packed f32x2 helpers (sm_100+ PTX; emits FFMA2 in SASS) ----
__device__ __forceinline__ u64 pack2(float lo, float hi) {
    u64 r; asm("mov.b64 %0, {%1,%2};" : "=l"(r) : "f"(lo), "f"(hi)); return r;
}
__device__ __forceinline__ void unpack2(u64 v, float& lo, float& hi) {
    asm("mov.b64 {%0,%1}, %2;" : "=f"(lo), "=f"(hi) : "l"(v));
}
__device__ __forceinline__ u64 fma2(u64 a, u64 b, u64 c) {
    u64 r; asm("fma.rn.f32x2 %0, %1, %2, %3;" : "=l"(r) : "l"(a), "l"(b), "l"(c));
    return r;
}

__global__ void __launch_bounds__(128)
nerf_render_kernel(const float* __restrict__ o,
                   const float* __restrict__ d,
                   const float* __restrict__ tnear,
                   const float* __restrict__ tfar,
                   const float* __restrict__ noise,
                   const float* __restrict__ W1,      // (3,16)
                   const float* __restrict__ b1,      // (16)
                   const float* __restrict__ w_sigma, // (16,1)
                   const float* __restrict__ W_rgb,   // (16,3)
                   float* __restrict__ out,           // (N,5)
                   int N)
{
    const int ray = blockIdx.x * blockDim.x + threadIdx.x;
    if (ray >= N) return;

    // ---- packed weights: pair of adjacent hidden units per 64-bit reg ----
    u64 w1x2[HPAIRS], w1y2[HPAIRS], w1z2[HPAIRS], b2[HPAIRS], ws2[HPAIRS];
    u64 wr0_2[HPAIRS], wr1_2[HPAIRS], wr2_2[HPAIRS];
#pragma unroll
    for (int p = 0; p < HPAIRS; p++) {
        const int j = 2 * p;
        w1x2[p]  = pack2(__ldg(&W1[0 * HID + j]), __ldg(&W1[0 * HID + j + 1]));
        w1y2[p]  = pack2(__ldg(&W1[1 * HID + j]), __ldg(&W1[1 * HID + j + 1]));
        w1z2[p]  = pack2(__ldg(&W1[2 * HID + j]), __ldg(&W1[2 * HID + j + 1]));
        b2[p]    = pack2(__ldg(&b1[j]), __ldg(&b1[j + 1]));
        ws2[p]   = pack2(__ldg(&w_sigma[j]), __ldg(&w_sigma[j + 1]));
        wr0_2[p] = pack2(__ldg(&W_rgb[j * 3 + 0]), __ldg(&W_rgb[(j + 1) * 3 + 0]));
        wr1_2[p] = pack2(__ldg(&W_rgb[j * 3 + 1]), __ldg(&W_rgb[(j + 1) * 3 + 1]));
        wr2_2[p] = pack2(__ldg(&W_rgb[j * 3 + 2]), __ldg(&W_rgb[(j + 1) * 3 + 2]));
    }

    // ---- per-ray state ----
    const float ox = o[3 * ray + 0], oy = o[3 * ray + 1], oz = o[3 * ray + 2];
    const float dx = d[3 * ray + 0], dy = d[3 * ray + 1], dz = d[3 * ray + 2];
    const float dn = sqrtf(dx * dx + dy * dy + dz * dz);
    const float tn = tnear[ray];
    const float tf = tfar[ray];
    const float step = (tf - tn) * (1.0f / (float)T_SAMPLES);

    float ts_prev = fmaf(step, noise[ray], tn);

    float Ttr = 1.0f;
    float c0 = 0.f, c1 = 0.f, c2 = 0.f, dep = 0.f, alp = 0.f;

#pragma unroll 2
    for (int t = 1; t <= T_SAMPLES; t++) {
        float ts;
        if (t < T_SAMPLES) {
            const float u = noise[(size_t)t * N + ray];
            ts = fmaf(step, (float)t + u, tn);
        } else {
            ts = tf;
        }
        const float delta = ts - ts_prev;

        // ---- MLP at ts_prev, hidden dim packed 2-wide ----
        const float x = fmaf(ts_prev, dx, ox);
        const float y = fmaf(ts_prev, dy, oy);
        const float z = fmaf(ts_prev, dz, oz);
        const u64 xp = pack2(x, x);
        const u64 yp = pack2(y, y);
        const u64 zp = pack2(z, z);

        u64 accs2 = 0ull, r0p = 0ull, r1p = 0ull, r2p = 0ull;  // packed {+0,+0}
#pragma unroll
        for (int p = 0; p < HPAIRS; p++) {
            u64 hp = fma2(xp, w1x2[p], fma2(yp, w1y2[p], fma2(zp, w1z2[p], b2[p])));
            float hl, hh;
            unpack2(hp, hl, hh);
            hl = fmaxf(hl, 0.0f);          // FMNMX -> alu pipe
            hh = fmaxf(hh, 0.0f);
            hp = pack2(hl, hh);
            accs2 = fma2(hp, ws2[p],   accs2);
            r0p   = fma2(hp, wr0_2[p], r0p);
            r1p   = fma2(hp, wr1_2[p], r1p);
            r2p   = fma2(hp, wr2_2[p], r2p);
        }

        float al, ah, r0l, r0h, r1l, r1h, r2l, r2h;
        unpack2(accs2, al, ah);
        unpack2(r0p, r0l, r0h);
        unpack2(r1p, r1l, r1h);
        unpack2(r2p, r2l, r2h);
        const float acc_s = al + ah;
        const float r0 = r0l + r0h, r1 = r1l + r1h, r2 = r2l + r2h;

        // softplus (stable): max(a,0) + log(1 + exp(-|a|))
        const float sigma = fmaxf(acc_s, 0.0f)
                          + __logf(1.0f + __expf(-fabsf(acc_s)));
        const float sd = sigma * delta * dn;
        const float e  = __expf(-sd);
        const float w  = Ttr * (1.0f - e);
        Ttr *= e;

        const float s0 = __fdividef(1.0f, 1.0f + __expf(-r0));
        const float s1 = __fdividef(1.0f, 1.0f + __expf(-r1));
        const float s2 = __fdividef(1.0f, 1.0f + __expf(-r2));

        c0  = fmaf(w, s0, c0);
        c1  = fmaf(w, s1, c1);
        c2  = fmaf(w, s2, c2);
        dep = fmaf(w, ts_prev, dep);
        alp += w;

        ts_prev = ts;
    }

    out[5 * ray + 0] = c0;
    out[5 * ray + 1] = c1;
    out[5 * ray + 2] = c2;
    out[5 * ray + 3] = dep;
    out[5 * ray + 4] = alp;
}

extern "C" void kernel_launch(void* const* d_in, const int* in_sizes, int n_in,
                              void* d_out, int out_size)
{
    const float* o       = (const float*)d_in[0];
    const float* d       = (const float*)d_in[1];
    const float* tnear   = (const float*)d_in[2];
    const float* tfar    = (const float*)d_in[3];
    const float* noise   = (const float*)d_in[4];
    const float* W1      = (const float*)d_in[5];
    const float* b1      = (const float*)d_in[6];
    const float* w_sigma = (const float*)d_in[7];
    const float* W_rgb   = (const float*)d_in[8];
    float* out = (float*)d_out;

    const int N = in_sizes[2];  // tnear element count
    const int threads = 128;
    const int blocks = (N + threads - 1) / threads;
    nerf_render_kernel<<<blocks, threads>>>(o, d, tnear, tfar, noise,
                                            W1, b1, w_sigma, W_rgb, out, N);
}

// round 3
// speedup vs baseline: 1.6194x; 1.6194x over previous
#include <cuda_runtime.h>
#include <math.h>

#define T_SAMPLES 128
#define HID 16
#define HPAIRS (HID / 2)

typedef unsigned long long u64;

// ---- packed f32x2 helpers (sm_100+; emits FFMA2 in SASS) ----
__device__ __forceinline__ u64 pack2(float lo, float hi) {
    u64 r; asm("mov.b64 %0, {%1,%2};" : "=l"(r) : "f"(lo), "f"(hi)); return r;
}
__device__ __forceinline__ void unpack2(u64 v, float& lo, float& hi) {
    asm("mov.b64 {%0,%1}, %2;" : "=f"(lo), "=f"(hi) : "l"(v));
}
__device__ __forceinline__ u64 fma2(u64 a, u64 b, u64 c) {
    u64 r; asm("fma.rn.f32x2 %0, %1, %2, %3;" : "=l"(r) : "l"(a), "l"(b), "l"(c));
    return r;
}

__global__ void __launch_bounds__(256, 2)
nerf_render_kernel(const float* __restrict__ o,
                   const float* __restrict__ d,
                   const float* __restrict__ tnear,
                   const float* __restrict__ tfar,
                   const float* __restrict__ noise,
                   const float* __restrict__ W1,      // (3,16)
                   const float* __restrict__ b1,      // (16)
                   const float* __restrict__ w_sigma, // (16,1)
                   const float* __restrict__ W_rgb,   // (16,3)
                   float* __restrict__ out,           // (N,5)
                   int N)
{
    const int ray = blockIdx.x * blockDim.x + threadIdx.x;
    if (ray >= N) return;

    // ---- per-ray geometry ----
    const float ox = o[3 * ray + 0], oy = o[3 * ray + 1], oz = o[3 * ray + 2];
    const float dx = d[3 * ray + 0], dy = d[3 * ray + 1], dz = d[3 * ray + 2];
    const float dn = sqrtf(dx * dx + dy * dy + dz * dz);
    const float tn = tnear[ray];
    const float tf = tfar[ray];
    const float step = (tf - tn) * (1.0f / (float)T_SAMPLES);

    // ---- fold ray into layer-1: pre_j(t) = A_j + t * B_j ----
    // A_j = o . W1[:,j] + b1_j ;  B_j = d . W1[:,j]
    u64 Ap[HPAIRS], Bp[HPAIRS];
    u64 ws2[HPAIRS], wr0_2[HPAIRS], wr1_2[HPAIRS], wr2_2[HPAIRS];
#pragma unroll
    for (int p = 0; p < HPAIRS; p++) {
        const int j = 2 * p;
        const float w1x0 = __ldg(&W1[0 * HID + j]), w1x1 = __ldg(&W1[0 * HID + j + 1]);
        const float w1y0 = __ldg(&W1[1 * HID + j]), w1y1 = __ldg(&W1[1 * HID + j + 1]);
        const float w1z0 = __ldg(&W1[2 * HID + j]), w1z1 = __ldg(&W1[2 * HID + j + 1]);
        const float A0 = fmaf(ox, w1x0, fmaf(oy, w1y0, fmaf(oz, w1z0, __ldg(&b1[j]))));
        const float A1 = fmaf(ox, w1x1, fmaf(oy, w1y1, fmaf(oz, w1z1, __ldg(&b1[j + 1]))));
        const float B0 = fmaf(ox * 0.f + dx, w1x0, fmaf(dy, w1y0, dz * w1z0));
        const float B1 = fmaf(dx, w1x1, fmaf(dy, w1y1, dz * w1z1));
        Ap[p] = pack2(A0, A1);
        Bp[p] = pack2(B0, B1);
        ws2[p]   = pack2(__ldg(&w_sigma[j]), __ldg(&w_sigma[j + 1]));
        wr0_2[p] = pack2(__ldg(&W_rgb[j * 3 + 0]), __ldg(&W_rgb[(j + 1) * 3 + 0]));
        wr1_2[p] = pack2(__ldg(&W_rgb[j * 3 + 1]), __ldg(&W_rgb[(j + 1) * 3 + 1]));
        wr2_2[p] = pack2(__ldg(&W_rgb[j * 3 + 2]), __ldg(&W_rgb[(j + 1) * 3 + 2]));
    }

    float ts_prev = fmaf(step, noise[ray], tn);

    float Ttr = 1.0f;
    float c0 = 0.f, c1 = 0.f, c2 = 0.f, dep = 0.f, alp = 0.f;

#pragma unroll 2
    for (int t = 1; t <= T_SAMPLES; t++) {
        float ts;
        if (t < T_SAMPLES) {
            const float u = noise[(size_t)t * N + ray];
            ts = fmaf(step, (float)t + u, tn);
        } else {
            ts = tf;
        }
        const float delta = ts - ts_prev;

        const u64 tp = pack2(ts_prev, ts_prev);

        u64 accs2 = 0ull, r0p = 0ull, r1p = 0ull, r2p = 0ull;
#pragma unroll
        for (int p = 0; p < HPAIRS; p++) {
            u64 hp = fma2(tp, Bp[p], Ap[p]);        // layer 1: one FFMA2
            float hl, hh;
            unpack2(hp, hl, hh);
            hl = fmaxf(hl, 0.0f);                   // relu -> alu pipe
            hh = fmaxf(hh, 0.0f);
            hp = pack2(hl, hh);
            accs2 = fma2(hp, ws2[p],   accs2);
            r0p   = fma2(hp, wr0_2[p], r0p);
            r1p   = fma2(hp, wr1_2[p], r1p);
            r2p   = fma2(hp, wr2_2[p], r2p);
        }

        float al, ah, r0l, r0h, r1l, r1h, r2l, r2h;
        unpack2(accs2, al, ah);
        unpack2(r0p, r0l, r0h);
        unpack2(r1p, r1l, r1h);
        unpack2(r2p, r2l, r2h);
        const float acc_s = al + ah;
        const float r0 = r0l + r0h, r1 = r1l + r1h, r2 = r2l + r2h;

        // softplus (stable): max(a,0) + log(1 + exp(-|a|))
        const float sigma = fmaxf(acc_s, 0.0f)
                          + __logf(1.0f + __expf(-fabsf(acc_s)));
        const float sd = sigma * delta * dn;
        const float e  = __expf(-sd);
        const float w  = Ttr * (1.0f - e);
        Ttr *= e;

        const float s0 = __fdividef(1.0f, 1.0f + __expf(-r0));
        const float s1 = __fdividef(1.0f, 1.0f + __expf(-r1));
        const float s2 = __fdividef(1.0f, 1.0f + __expf(-r2));

        c0  = fmaf(w, s0, c0);
        c1  = fmaf(w, s1, c1);
        c2  = fmaf(w, s2, c2);
        dep = fmaf(w, ts_prev, dep);
        alp += w;

        ts_prev = ts;
    }

    out[5 * ray + 0] = c0;
    out[5 * ray + 1] = c1;
    out[5 * ray + 2] = c2;
    out[5 * ray + 3] = dep;
    out[5 * ray + 4] = alp;
}

extern "C" void kernel_launch(void* const* d_in, const int* in_sizes, int n_in,
                              void* d_out, int out_size)
{
    const float* o       = (const float*)d_in[0];
    const float* d       = (const float*)d_in[1];
    const float* tnear   = (const float*)d_in[2];
    const float* tfar    = (const float*)d_in[3];
    const float* noise   = (const float*)d_in[4];
    const float* W1      = (const float*)d_in[5];
    const float* b1      = (const float*)d_in[6];
    const float* w_sigma = (const float*)d_in[7];
    const float* W_rgb   = (const float*)d_in[8];
    float* out = (float*)d_out;

    const int N = in_sizes[2];  // tnear element count
    const int threads = 256;
    const int blocks = (N + threads - 1) / threads;
    nerf_render_kernel<<<blocks, threads>>>(o, d, tnear, tfar, noise,
                                            W1, b1, w_sigma, W_rgb, out, N);
}